// round 7
// baseline (speedup 1.0000x reference)
#include <cuda_runtime.h>
#include <cuda_bf16.h>

#define N_NODES 50000
#define N_EDGES 1600000
#define DIM 128
#define NODES_PER_BLOCK 64
#define THREADS 256

// CSR row offsets scratch (allocation-free: __device__ global)
__device__ int g_row_off[N_NODES + 1];

// packed f32x2 FMA: d += a*b (two fp32 lanes per instruction)
#define FFMA2(d, a, b) asm("fma.rn.f32x2 %0, %1, %2, %0;" : "+l"(d) : "l"(a), "l"(b))

__device__ __forceinline__ unsigned long long dup2(float v) {
    unsigned long long d;
    unsigned u = __float_as_uint(v);
    asm("mov.b64 %0, {%1, %1};" : "=l"(d) : "r"(u));
    return d;
}
__device__ __forceinline__ float lo32(unsigned long long v) {
    return __uint_as_float((unsigned)v);
}
__device__ __forceinline__ float hi32(unsigned long long v) {
    return __uint_as_float((unsigned)(v >> 32));
}

// ---------------- Kernel A: offsets via coalesced boundary scan ----------------
__global__ void scan_offsets_kernel(const int* __restrict__ dst) {
    int i = blockIdx.x * blockDim.x + threadIdx.x;
    if (i >= N_EDGES) return;
    const int d = dst[i];
    const int prev = (i == 0) ? -1 : dst[i - 1];
    for (int j = prev + 1; j <= d; j++) g_row_off[j] = i;
    if (i == N_EDGES - 1) {
        for (int j = d + 1; j <= N_NODES; j++) g_row_off[j] = N_EDGES;
    }
}

// ---------------- Kernel B: fused aggregate + f32x2 SGEMM epilogue ----------------
__global__ __launch_bounds__(THREADS, 3)
void gcn_fused_kernel(const float* __restrict__ H,
                      const int* __restrict__ esrc,
                      const float* __restrict__ ew,
                      const float* __restrict__ W,
                      const float* __restrict__ bias,
                      float* __restrict__ out)
{
    // aggregate, stored duplicated: sAgg2[row][k] = (a, a) packed f32x2. 64 KB.
    __shared__ unsigned long long sAgg2[NODES_PER_BLOCK][DIM];

    const int tid  = threadIdx.x;
    const int wid  = tid >> 5;
    const int lane = tid & 31;
    const int base = blockIdx.x * NODES_PER_BLOCK;

    const float4* __restrict__ H4 = (const float4*)H;

    // -------- Aggregation: warp owns 8 consecutive nodes, pipelined across nodes --------
    const int nodeBase = base + wid * 8;

    // lanes 0..8 hold the 9 row offsets for this warp's 8 nodes (clamped at N_NODES)
    int off_l = 0;
    {
        int q = nodeBase + lane;
        if (q > N_NODES) q = N_NODES;
        if (lane <= 8) off_l = g_row_off[q];
    }

    // prefetch node 0's first edge strip
    int s_cur = __shfl_sync(0xffffffffu, off_l, 0);
    int e_cur = __shfl_sync(0xffffffffu, off_l, 1);
    int   src_c = 0;
    float w_c   = 0.f;
    if (s_cur + lane < e_cur) { src_c = esrc[s_cur + lane]; w_c = ew[s_cur + lane]; }

    #pragma unroll 1
    for (int r = 0; r < 8; r++) {
        const int s = s_cur;
        const int e = e_cur;

        // prefetch NEXT node's first strip (independent of this node's work)
        int   src_n = 0;
        float w_n   = 0.f;
        int   s_nxt = 0, e_nxt = 0;
        if (r < 7) {
            s_nxt = __shfl_sync(0xffffffffu, off_l, r + 1);
            e_nxt = __shfl_sync(0xffffffffu, off_l, r + 2);
            if (s_nxt + lane < e_nxt) { src_n = esrc[s_nxt + lane]; w_n = ew[s_nxt + lane]; }
        }

        unsigned long long acc0 = 0ull, acc1 = 0ull;   // cols (4l,4l+1),(4l+2,4l+3)
        int   src = src_c;
        float w   = w_c;

        #pragma unroll 1
        for (int p = s; p < e; p += 32) {
            const int cnt = min(32, e - p);

            // prefetch next strip within this node (deg > 32)
            int   srcN = 0;
            float wN   = 0.f;
            const int pn = p + 32;
            if (pn + lane < e) { srcN = esrc[pn + lane]; wN = ew[pn + lane]; }

            if (cnt == 32) {
                #pragma unroll
                for (int g = 0; g < 32; g += 4) {
                    int   ss[4];
                    float ws[4];
                    #pragma unroll
                    for (int i = 0; i < 4; i++) {
                        ss[i] = __shfl_sync(0xffffffffu, src, g + i);
                        ws[i] = __shfl_sync(0xffffffffu, w,   g + i);
                    }
                    float4 hh[4];
                    #pragma unroll
                    for (int i = 0; i < 4; i++)
                        hh[i] = H4[(size_t)ss[i] * 32 + lane];
                    #pragma unroll
                    for (int i = 0; i < 4; i++) {
                        const unsigned long long wd = dup2(ws[i]);
                        ulonglong2 hp = *(const ulonglong2*)&hh[i];
                        FFMA2(acc0, wd, hp.x);
                        FFMA2(acc1, wd, hp.y);
                    }
                }
            } else {
                // partial strip: zero-padded 4-deep groups (pad lanes carry w=0,src=0)
                #pragma unroll 1
                for (int g = 0; g < cnt; g += 4) {
                    int   ss[4];
                    float ws[4];
                    #pragma unroll
                    for (int i = 0; i < 4; i++) {
                        ss[i] = __shfl_sync(0xffffffffu, src, g + i);
                        ws[i] = __shfl_sync(0xffffffffu, w,   g + i);
                    }
                    float4 hh[4];
                    #pragma unroll
                    for (int i = 0; i < 4; i++)
                        hh[i] = H4[(size_t)ss[i] * 32 + lane];
                    #pragma unroll
                    for (int i = 0; i < 4; i++) {
                        const unsigned long long wd = dup2(ws[i]);
                        ulonglong2 hp = *(const ulonglong2*)&hh[i];
                        FFMA2(acc0, wd, hp.x);
                        FFMA2(acc1, wd, hp.y);
                    }
                }
            }
            src = srcN;
            w   = wN;
        }

        // unpack + duplicate each scalar, store 4 dup'd values (32 B per lane)
        ulonglong2 d0, d1;
        d0.x = dup2(lo32(acc0)); d0.y = dup2(hi32(acc0));
        d1.x = dup2(lo32(acc1)); d1.y = dup2(hi32(acc1));
        const int rowLocal = wid * 8 + r;
        *(ulonglong2*)&sAgg2[rowLocal][4 * lane]     = d0;
        *(ulonglong2*)&sAgg2[rowLocal][4 * lane + 2] = d1;

        // roll the cross-node pipeline
        s_cur = s_nxt; e_cur = e_nxt;
        src_c = src_n; w_c = w_n;
    }

    __syncthreads();

    // -------- f32x2 GEMM epilogue: C[64x128] = Agg @ W + b --------
    // warp ty owns rows ty*8..ty*8+7; lane tx owns cols 4tx..4tx+3 (2 packed pairs)
    const int tx = lane;
    const int ty = wid;
    unsigned long long c[8][2];
    #pragma unroll
    for (int i = 0; i < 8; i++) { c[i][0] = 0ull; c[i][1] = 0ull; }

    const unsigned long long* __restrict__ Wp = (const unsigned long long*)W;

    #pragma unroll 4
    for (int k = 0; k < DIM; k += 2) {
        // W rows k, k+1, this lane's 4 cols as 2 packed pairs each (L1-resident)
        const ulonglong2 w0 = *(const ulonglong2*)(Wp + (size_t)(k + 0) * 64 + tx * 2);
        const ulonglong2 w1 = *(const ulonglong2*)(Wp + (size_t)(k + 1) * 64 + tx * 2);
        #pragma unroll
        for (int i = 0; i < 8; i++) {
            const int r = ty * 8 + i;
            // dup(a_k), dup(a_k+1): one broadcast LDS.128
            const ulonglong2 A = *(const ulonglong2*)&sAgg2[r][k];
            FFMA2(c[i][0], A.x, w0.x); FFMA2(c[i][1], A.x, w0.y);
            FFMA2(c[i][0], A.y, w1.x); FFMA2(c[i][1], A.y, w1.y);
        }
    }

    const float4 bb = ((const float4*)bias)[tx];
    #pragma unroll
    for (int i = 0; i < 8; i++) {
        const int row = base + ty * 8 + i;
        if (row < N_NODES) {
            float4 o;
            o.x = lo32(c[i][0]) + bb.x;
            o.y = hi32(c[i][0]) + bb.y;
            o.z = lo32(c[i][1]) + bb.z;
            o.w = hi32(c[i][1]) + bb.w;
            ((float4*)(out + (size_t)row * DIM))[tx] = o;
        }
    }
}

extern "C" void kernel_launch(void* const* d_in, const int* in_sizes, int n_in,
                              void* d_out, int out_size) {
    const float* H    = (const float*)d_in[0];
    const int*   esrc = (const int*)  d_in[1];
    const int*   edst = (const int*)  d_in[2];
    const float* ew   = (const float*)d_in[3];
    const float* W    = (const float*)d_in[4];
    const float* b    = (const float*)d_in[5];
    float* out = (float*)d_out;

    scan_offsets_kernel<<<(N_EDGES + 255) / 256, 256>>>(edst);

    const int nblocks = (N_NODES + NODES_PER_BLOCK - 1) / NODES_PER_BLOCK;
    gcn_fused_kernel<<<nblocks, THREADS>>>(H, esrc, ew, W, b, out);
}

// round 8
// speedup vs baseline: 1.6072x; 1.6072x over previous
#include <cuda_runtime.h>
#include <cuda_bf16.h>

#define N_NODES 50000
#define N_EDGES 1600000
#define DIM 128
#define NODES_PER_BLOCK 64
#define THREADS 256

// CSR row offsets scratch (allocation-free: __device__ global)
__device__ int g_row_off[N_NODES + 1];

// packed f32x2 FMA: d += a*b (two fp32 lanes per instruction)
#define FFMA2(d, a, b) asm("fma.rn.f32x2 %0, %1, %2, %0;" : "+l"(d) : "l"(a), "l"(b))

__device__ __forceinline__ unsigned long long dup2(float v) {
    unsigned long long d;
    unsigned u = __float_as_uint(v);
    asm("mov.b64 %0, {%1, %1};" : "=l"(d) : "r"(u));
    return d;
}
__device__ __forceinline__ float lo32(unsigned long long v) {
    return __uint_as_float((unsigned)v);
}
__device__ __forceinline__ float hi32(unsigned long long v) {
    return __uint_as_float((unsigned)(v >> 32));
}

// ---------------- Kernel A: offsets via coalesced boundary scan ----------------
__global__ void scan_offsets_kernel(const int* __restrict__ dst) {
    int i = blockIdx.x * blockDim.x + threadIdx.x;
    if (i >= N_EDGES) return;
    const int d = dst[i];
    const int prev = (i == 0) ? -1 : dst[i - 1];
    for (int j = prev + 1; j <= d; j++) g_row_off[j] = i;
    if (i == N_EDGES - 1) {
        for (int j = d + 1; j <= N_NODES; j++) g_row_off[j] = N_EDGES;
    }
}

// ---------------- Kernel B: fused aggregate + warp-private f32x2 epilogue ----------------
// No __syncthreads: each warp aggregates its own 8 rows into its own smem slice,
// then immediately runs the GEMM epilogue for those rows. Warps desynchronize,
// overlapping L1-heavy gather with FMA-heavy GEMM across warps.
__global__ __launch_bounds__(THREADS, 3)
void gcn_fused_kernel(const float* __restrict__ H,
                      const int* __restrict__ esrc,
                      const float* __restrict__ ew,
                      const float* __restrict__ W,
                      const float* __restrict__ bias,
                      float* __restrict__ out)
{
    // per-warp 8-row slices, stored duplicated: sAgg2[row][k] = (a, a) f32x2. 64 KB.
    __shared__ unsigned long long sAgg2[NODES_PER_BLOCK][DIM];

    const int tid  = threadIdx.x;
    const int wid  = tid >> 5;
    const int lane = tid & 31;
    const int base = blockIdx.x * NODES_PER_BLOCK;

    const float4* __restrict__ H4 = (const float4*)H;

    // -------- Aggregation: warp handles its 8 consecutive nodes --------
    #pragma unroll 1
    for (int r = 0; r < NODES_PER_BLOCK / 8; r++) {
        const int rowLocal = wid * 8 + r;
        const int node = base + rowLocal;
        unsigned long long acc0 = 0ull, acc1 = 0ull;   // cols (4l,4l+1),(4l+2,4l+3)

        if (node < N_NODES) {
            const int s = g_row_off[node];
            const int e = g_row_off[node + 1];
            #pragma unroll 1
            for (int p = s; p < e; p += 32) {
                const int idx = p + lane;
                int   src = 0;
                float w   = 0.f;     // zero-pad: lanes past end contribute nothing
                if (idx < e) { src = esrc[idx]; w = ew[idx]; }
                const int cnt = min(32, e - p);
                if (cnt == 32) {
                    #pragma unroll
                    for (int g = 0; g < 32; g += 4) {
                        int   ss[4];
                        float ws[4];
                        #pragma unroll
                        for (int i = 0; i < 4; i++) {
                            ss[i] = __shfl_sync(0xffffffffu, src, g + i);
                            ws[i] = __shfl_sync(0xffffffffu, w,   g + i);
                        }
                        float4 hh[4];
                        #pragma unroll
                        for (int i = 0; i < 4; i++)
                            hh[i] = H4[(size_t)ss[i] * 32 + lane];
                        #pragma unroll
                        for (int i = 0; i < 4; i++) {
                            const unsigned long long wd = dup2(ws[i]);
                            ulonglong2 hp = *(const ulonglong2*)&hh[i];
                            FFMA2(acc0, wd, hp.x);
                            FFMA2(acc1, wd, hp.y);
                        }
                    }
                } else {
                    // partial strip: zero-padded 4-deep groups
                    #pragma unroll 1
                    for (int g = 0; g < cnt; g += 4) {
                        int   ss[4];
                        float ws[4];
                        #pragma unroll
                        for (int i = 0; i < 4; i++) {
                            ss[i] = __shfl_sync(0xffffffffu, src, g + i);
                            ws[i] = __shfl_sync(0xffffffffu, w,   g + i);
                        }
                        float4 hh[4];
                        #pragma unroll
                        for (int i = 0; i < 4; i++)
                            hh[i] = H4[(size_t)ss[i] * 32 + lane];
                        #pragma unroll
                        for (int i = 0; i < 4; i++) {
                            const unsigned long long wd = dup2(ws[i]);
                            ulonglong2 hp = *(const ulonglong2*)&hh[i];
                            FFMA2(acc0, wd, hp.x);
                            FFMA2(acc1, wd, hp.y);
                        }
                    }
                }
            }
        }
        // unpack + duplicate each scalar, store 4 dup'd values (32 B per lane)
        ulonglong2 d0, d1;
        d0.x = dup2(lo32(acc0)); d0.y = dup2(hi32(acc0));
        d1.x = dup2(lo32(acc1)); d1.y = dup2(hi32(acc1));
        *(ulonglong2*)&sAgg2[rowLocal][4 * lane]     = d0;
        *(ulonglong2*)&sAgg2[rowLocal][4 * lane + 2] = d1;
    }

    __syncwarp();   // intra-warp smem visibility only; no block barrier

    // -------- f32x2 GEMM epilogue for THIS warp's 8 rows --------
    // lane tx owns cols 4tx..4tx+3 (2 packed pairs)
    const int tx = lane;
    const int ty = wid;
    unsigned long long c[8][2];
    #pragma unroll
    for (int i = 0; i < 8; i++) { c[i][0] = 0ull; c[i][1] = 0ull; }

    const unsigned long long* __restrict__ Wp = (const unsigned long long*)W;

    #pragma unroll 4
    for (int k = 0; k < DIM; k += 2) {
        // W rows k, k+1, this lane's 4 cols as 2 packed pairs each (L1-resident)
        const ulonglong2 w0 = *(const ulonglong2*)(Wp + (size_t)(k + 0) * 64 + tx * 2);
        const ulonglong2 w1 = *(const ulonglong2*)(Wp + (size_t)(k + 1) * 64 + tx * 2);
        #pragma unroll
        for (int i = 0; i < 8; i++) {
            const int r = ty * 8 + i;
            // dup(a_k), dup(a_k+1): one broadcast LDS.128
            const ulonglong2 A = *(const ulonglong2*)&sAgg2[r][k];
            FFMA2(c[i][0], A.x, w0.x); FFMA2(c[i][1], A.x, w0.y);
            FFMA2(c[i][0], A.y, w1.x); FFMA2(c[i][1], A.y, w1.y);
        }
    }

    const float4 bb = ((const float4*)bias)[tx];
    #pragma unroll
    for (int i = 0; i < 8; i++) {
        const int row = base + ty * 8 + i;
        if (row < N_NODES) {
            float4 o;
            o.x = lo32(c[i][0]) + bb.x;
            o.y = hi32(c[i][0]) + bb.y;
            o.z = lo32(c[i][1]) + bb.z;
            o.w = hi32(c[i][1]) + bb.w;
            ((float4*)(out + (size_t)row * DIM))[tx] = o;
        }
    }
}

extern "C" void kernel_launch(void* const* d_in, const int* in_sizes, int n_in,
                              void* d_out, int out_size) {
    const float* H    = (const float*)d_in[0];
    const int*   esrc = (const int*)  d_in[1];
    const int*   edst = (const int*)  d_in[2];
    const float* ew   = (const float*)d_in[3];
    const float* W    = (const float*)d_in[4];
    const float* b    = (const float*)d_in[5];
    float* out = (float*)d_out;

    scan_offsets_kernel<<<(N_EDGES + 255) / 256, 256>>>(edst);

    const int nblocks = (N_NODES + NODES_PER_BLOCK - 1) / NODES_PER_BLOCK;
    gcn_fused_kernel<<<nblocks, THREADS>>>(H, esrc, ew, W, b, out);
}